// round 17
// baseline (speedup 1.0000x reference)
#include <cuda_runtime.h>
#include <cuda_fp16.h>
#include <cstdint>

#define BB 4
#define CC 256
#define HH 56
#define WW 56
#define CO 128
#define NT 49
#define HW 3136
#define GTOT 392          // 49 taps x 8 ci-blocks of 32
#define KSPL 3
#define XPR 68            // padded image 68x68
#define XPCH (XPR * XPR)  // 4624
#define NPC (BB * CC * XPCH)

typedef unsigned long long u64;

// ---- device-global scratch ----
__device__ __align__(16) __half g_W1bh[GTOT * 4096];         // half weights [g][co][k]
__device__ __align__(16) __half g_xh[2 * NPC];               // padded x half, 2 parities
__device__ __align__(16) __half g_parth[KSPL * BB * CO * HW];// conv1 K-split partials (fp16)
__device__ __align__(16) float  g_attn[BB * NT * HW];        // softmax attention

// ---------- helpers ----------
__device__ __forceinline__ uint32_t smem_to_u32(const void* p) {
    uint32_t a;
    asm("{ .reg .u64 t; cvta.to.shared.u64 t, %1; cvt.u32.u64 %0, t; }" : "=r"(a) : "l"(p));
    return a;
}
#define CP16(dst, src) \
    asm volatile("cp.async.cg.shared.global [%0], [%1], 16;" :: "r"(dst), "l"(src) : "memory")
#define CP8(dst, src) \
    asm volatile("cp.async.ca.shared.global [%0], [%1], 8;" :: "r"(dst), "l"(src) : "memory")
#define CP_COMMIT() asm volatile("cp.async.commit_group;" ::: "memory")
#define CP_WAIT0()  asm volatile("cp.async.wait_group 0;" ::: "memory")
#define CP_WAIT2()  asm volatile("cp.async.wait_group 2;" ::: "memory")

#define LDMX4T(r, addr) \
    asm volatile("ldmatrix.sync.aligned.m8n8.x4.trans.shared.b16 {%0,%1,%2,%3}, [%4];" \
        : "=r"((r)[0]), "=r"((r)[1]), "=r"((r)[2]), "=r"((r)[3]) : "r"(addr))
#define LDMX2(r, addr) \
    asm volatile("ldmatrix.sync.aligned.m8n8.x2.shared.b16 {%0,%1}, [%2];" \
        : "=r"((r)[0]), "=r"((r)[1]) : "r"(addr))

#define MMA_F16(d, a, b) \
    asm volatile("mma.sync.aligned.m16n8k16.row.col.f32.f16.f16.f32 " \
        "{%0,%1,%2,%3}, {%4,%5,%6,%7}, {%8,%9}, {%0,%1,%2,%3};" \
        : "+f"((d)[0]), "+f"((d)[1]), "+f"((d)[2]), "+f"((d)[3]) \
        : "r"((a)[0]), "r"((a)[1]), "r"((a)[2]), "r"((a)[3]), \
          "r"((b)[0]), "r"((b)[1]))

// ---------- f32x2 helpers for scalar kernels ----------
__device__ __forceinline__ void fma2(u64& d, u64 a, u64 b) {
    asm("fma.rn.f32x2 %0, %1, %2, %0;" : "+l"(d) : "l"(a), "l"(b));
}
__device__ __forceinline__ float2 unpack2(u64 v) {
    float2 f;
    asm("mov.b64 {%0, %1}, %2;" : "=f"(f.x), "=f"(f.y) : "l"(v));
    return f;
}
__device__ __forceinline__ u64 pack2f(float2 f) {
    u64 r;
    asm("mov.b64 %0, {%1, %2};" : "=l"(r) : "f"(f.x), "f"(f.y));
    return r;
}
__device__ __forceinline__ u64 lds64(const float* p) {
    return *reinterpret_cast<const u64*>(p);
}

// =====================================================================
// Kernel 0 (fused prep): blockIdx < 1024 -> W1 transpose-bake (coalesced);
// else -> zero-padded half x images (2 parities).
// =====================================================================
#define W1T_BLOCKS 1024
#define XPH_BLOCKS ((NPC / 2 + 255) / 256)

__global__ void __launch_bounds__(256) prep_all(const float* __restrict__ W1,
                                                const float* __restrict__ x)
{
    __shared__ float ws[1568];
    if (blockIdx.x < W1T_BLOCKS) {
        const int co = blockIdx.x >> 3, cib = blockIdx.x & 7;
        const float* src = W1 + ((size_t)co * CC + cib * 32) * NT;
        for (int t = threadIdx.x; t < 1568; t += 256) ws[t] = __ldg(src + t);
        __syncthreads();
        for (int t = threadIdx.x; t < 1568; t += 256) {
            int tap = t >> 5, k = t & 31;
            g_W1bh[(size_t)(tap * 8 + cib) * 4096 + co * 32 + k] =
                __float2half_rn(ws[k * NT + tap]);
        }
    } else {
        int pc = (blockIdx.x - W1T_BLOCKS) * 256 + threadIdx.x;
        if (pc >= NPC / 2) return;
        int cp2 = pc % (XPR / 2);
        int col = cp2 * 2;
        int t = pc / (XPR / 2);
        int r = t % XPR;
        int bc = t / XPR;
        int rr = r - 6;
        float v0a = 0.f, v0b = 0.f, v1a = 0.f, v1b = 0.f;
        if ((unsigned)rr < HH) {
            const float* xr = x + (size_t)bc * HW + rr * WW;
            int ca = col - 6; if ((unsigned)ca < WW) v0a = __ldg(xr + ca);
            int cb = col - 5; if ((unsigned)cb < WW) v0b = __ldg(xr + cb);
            int cd = col - 4; if ((unsigned)cd < WW) v1a = __ldg(xr + cd);
            int ce = col - 3; if ((unsigned)ce < WW) v1b = __ldg(xr + ce);
        }
        size_t o = (size_t)bc * XPCH + r * XPR + col;
        *reinterpret_cast<half2*>(g_xh + o) = __floats2half2_rn(v0a, v0b);
        *reinterpret_cast<half2*>(g_xh + NPC + o) = __floats2half2_rn(v1a, v1b);
    }
}

// =====================================================================
// Kernel A: conv1 fp16 mma.m16n8k16 GEMM. Grid (49, 3), 256 threads
// (8 warps). CTA tile 256px x 128co; warp tile 64x64 (acc=128 regs).
// A: As[k][px] (ASTH=264 halfs); B: Bs[co][k] (BSTH=40). 6-stage pipe.
// =====================================================================
#define ASTH 264
#define A_BYTES (32 * ASTH * 2)          // 16896
#define BSTH 40
#define B_BYTES (128 * BSTH * 2)         // 10240
#define NST 6
#define CST 260
#define CONV1_SMEM (NST * (A_BYTES + B_BYTES))   // 162816

__global__ void __launch_bounds__(256, 1) conv1_mma()
{
    extern __shared__ __align__(16) char smem[];
    const uint32_t sb = smem_to_u32(smem);
    const uint32_t sbB0 = sb + NST * A_BYTES;

    const int tid = threadIdx.x;
    const int wid = tid >> 5, lane = tid & 31;
    const int m0 = (wid >> 1) * 64;       // M quarter (of 256)
    const int n0 = (wid & 1) * 64;        // N half

    const int q = blockIdx.y;
    const int gstart = (q == 0) ? 0 : (132 + 130 * (q - 1));
    const int nn = (q == 0) ? 132 : 130;

    const uint32_t arow = (lane & 7) + ((lane & 16) >> 1);
    const uint32_t acol = (lane & 8);
    const int l15 = lane & 15;
    const uint32_t brow = (l15 & 7);
    const uint32_t bk8 = (l15 & 8);

    // A-copy roles: kl = row slot 0..7, two pixel quads (qd, qd+32)
    const int kl = tid >> 5;
    const int qd0 = tid & 31, qd1 = qd0 + 32;
    int gp0 = blockIdx.x * 256 + qd0 * 4;
    int gp1 = blockIdx.x * 256 + qd1 * 4;
    const int b40 = gp0 / HW, rem40 = gp0 % HW;
    const int b41 = gp1 / HW, rem41 = gp1 % HW;
    const int h40 = rem40 / WW, w40 = rem40 % WW;
    const int h41 = rem41 / WW, w41 = rem41 % WW;
    const __half* const aBase0 = g_xh + (size_t)(b40 * CC + kl) * XPCH + h40 * XPR + w40;
    const __half* const aBase1 = g_xh + (size_t)(b41 * CC + kl) * XPCH + h41 * XPR + w41;
    const uint32_t a_dst0 = sb + (uint32_t)(kl * ASTH + qd0 * 4) * 2;
    const uint32_t a_dst1 = sb + (uint32_t)(kl * ASTH + qd1 * 4) * 2;

    auto issue = [&](int g, int s) {
        // ---- B: 10KB tile via CP16 (512 chunks, 2 per thread) ----
#pragma unroll
        for (int i2 = 0; i2 < 2; ++i2) {
            int c = tid + i2 * 256;
            int co = c >> 2, kq = c & 3;
            const __half* srcB = g_W1bh + (size_t)g * 4096 + co * 32 + kq * 8;
            CP16(sbB0 + (uint32_t)s * B_BYTES + (uint32_t)(co * BSTH + kq * 8) * 2,
                 (const char*)srcB);
        }
        // ---- A: 16KB patch tile via CP8 (2048 chunks, 8 per thread) ----
        int tap = g >> 3, cib = g & 7;
        int di = tap / 7, dj = tap - di * 7;
        int par = dj & 1;
        const size_t aoff = (par ? NPC : 0) + (size_t)(cib * 32) * XPCH
                          + di * (2 * XPR) + (2 * dj - 2 * par);
        const __half* sA0 = aBase0 + aoff;
        const __half* sA1 = aBase1 + aoff;
        uint32_t dA0 = a_dst0 + (uint32_t)s * A_BYTES;
        uint32_t dA1 = a_dst1 + (uint32_t)s * A_BYTES;
#pragma unroll
        for (int it = 0; it < 4; ++it) {
            CP8(dA0, (const char*)sA0);
            CP8(dA1, (const char*)sA1);
            dA0 += 8 * ASTH * 2;
            dA1 += 8 * ASTH * 2;
            sA0 += (size_t)8 * XPCH;
            sA1 += (size_t)8 * XPCH;
        }
        CP_COMMIT();
    };

    float acc[4][8][4];
#pragma unroll
    for (int i = 0; i < 4; ++i)
#pragma unroll
        for (int j = 0; j < 8; ++j)
#pragma unroll
            for (int c = 0; c < 4; ++c) acc[i][j][c] = 0.f;

    auto compute = [&](int s) {
        const uint32_t aS = sb + (uint32_t)s * A_BYTES
                          + (arow * ASTH + m0 + acol) * 2;
        const uint32_t bS = sbB0 + (uint32_t)s * B_BYTES
                          + ((n0 + brow) * BSTH + bk8) * 2;
#pragma unroll
        for (int ks = 0; ks < 2; ++ks) {
            const uint32_t aK = aS + ks * (16 * ASTH * 2);
            const uint32_t bK = bS + ks * 32;
            uint32_t af[4][4], bf[8][2];
#pragma unroll
            for (int i = 0; i < 4; ++i) LDMX4T(af[i], aK + 32 * i);
#pragma unroll
            for (int j = 0; j < 8; ++j) LDMX2(bf[j], bK + j * (8 * BSTH * 2));
#pragma unroll
            for (int i = 0; i < 4; ++i)
#pragma unroll
                for (int j = 0; j < 8; ++j)
                    MMA_F16(acc[i][j], af[i], bf[j]);
        }
    };

    issue(gstart + 0, 0);
    issue(gstart + 1, 1);
    issue(gstart + 2, 2);
    issue(gstart + 3, 3);

    for (int gi = 0; gi < nn; gi += 2) {
        if (gi + 2 < nn) { CP_WAIT2(); } else { CP_WAIT0(); }
        __syncthreads();
        compute(gi % NST);
        compute((gi + 1) % NST);
        if (gi + 4 < nn) issue(gstart + gi + 4, (gi + 4) % NST);
        if (gi + 5 < nn) issue(gstart + gi + 5, (gi + 5) % NST);
    }
    __syncthreads();

    // ---- epilogue: acc -> smem [co][px] (stride 260) -> fp16 STG ----
    float* const Cs = (float*)smem;
    {
        const int g8 = lane >> 2, t4 = lane & 3;
#pragma unroll
        for (int i = 0; i < 4; ++i)
#pragma unroll
            for (int j = 0; j < 8; ++j) {
                int row0 = m0 + 16 * i + g8;
                int col0 = n0 + 8 * j + 2 * t4;
                Cs[(col0)     * CST + row0]     = acc[i][j][0];
                Cs[(col0 + 1) * CST + row0]     = acc[i][j][1];
                Cs[(col0)     * CST + row0 + 8] = acc[i][j][2];
                Cs[(col0 + 1) * CST + row0 + 8] = acc[i][j][3];
            }
    }
    __syncthreads();

    {
        const int pxg = blockIdx.x * 256 + tid;
        const int b2 = pxg / HW, rem2 = pxg % HW;
        __half* base = g_parth + ((size_t)(q * BB + b2) * CO) * HW + rem2;
#pragma unroll 4
        for (int co = 0; co < CO; ++co)
            base[(size_t)co * HW] = __float2half_rn(Cs[co * CST + tid]);
    }
}

// =====================================================================
// Kernel B: conv2 (1x1, 128->49) + softmax, 4 lanes per pixel.
// (unchanged from round 16)
// =====================================================================
#define W2SL 1576
__global__ void __launch_bounds__(256) conv2_softmax_kernel(
    const float* __restrict__ W2, const float* __restrict__ b1,
    const float* __restrict__ b2)
{
    __shared__ float W2r[4 * W2SL];
    __shared__ float b2s[NT];
    __shared__ float b1s[CO];
    const int tid = threadIdx.x;

    for (int t = tid; t < 4 * NT * 32; t += 256) {
        int s = t / (NT * 32), r = t - s * (NT * 32);
        int kk = r >> 5, j = r & 31;
        W2r[s * W2SL + kk * 32 + j] = __ldg(&W2[kk * 128 + s * 32 + j]);
    }
    if (tid < NT) b2s[tid] = __ldg(&b2[tid]);
    if (tid < CO) b1s[tid] = __ldg(&b1[tid]);
    __syncthreads();

    const int wid = tid >> 5, lane = tid & 31;
    const int slice = lane >> 3, pl = lane & 7;
    const int px = blockIdx.x * 64 + wid * 8 + pl;
    const int b = px / HW, rem = px % HW;
    const int c0 = slice * 32;

    float acc[NT];
#pragma unroll
    for (int kk = 0; kk < NT; ++kk) acc[kk] = 0.f;

    const __half* p0 = g_parth + ((size_t)(0 * BB + b) * CO + c0) * HW + rem;
    const __half* p1 = g_parth + ((size_t)(1 * BB + b) * CO + c0) * HW + rem;
    const __half* p2 = g_parth + ((size_t)(2 * BB + b) * CO + c0) * HW + rem;
    const float* wbase = &W2r[slice * W2SL];

#pragma unroll 4
    for (int c = 0; c < 32; ++c) {
        float kv = __half2float(p0[(size_t)c * HW])
                 + __half2float(p1[(size_t)c * HW])
                 + __half2float(p2[(size_t)c * HW])
                 + b1s[c0 + c];
        const float* wc = wbase + c;
#pragma unroll
        for (int kk = 0; kk < NT; ++kk)
            acc[kk] = fmaf(kv, wc[kk * 32], acc[kk]);
    }

#pragma unroll
    for (int kk = 0; kk < NT; ++kk) {
        acc[kk] += __shfl_xor_sync(0xffffffffu, acc[kk], 8);
        acc[kk] += __shfl_xor_sync(0xffffffffu, acc[kk], 16);
        acc[kk] += b2s[kk];
    }

    float m = acc[0];
#pragma unroll
    for (int kk = 1; kk < NT; ++kk) m = fmaxf(m, acc[kk]);
    float s = 0.f;
#pragma unroll
    for (int kk = 0; kk < NT; ++kk) {
        acc[kk] = expf(acc[kk] - m);
        s += acc[kk];
    }
    float inv = 1.f / s;

    float* dst = g_attn + (size_t)b * NT * HW + rem;
    const int k_lo = (slice == 0) ? 0 : (13 + (slice - 1) * 12);
    const int k_hi = (slice == 0) ? 13 : (k_lo + 12);
    for (int kk = k_lo; kk < k_hi; ++kk)
        dst[(size_t)kk * HW] = acc[kk] * inv;
}

// =====================================================================
// Kernel C: weighted local sum over 49 dilated taps -> out
// (unchanged from round 16 — half x tiles, double-buffered cp.async)
// =====================================================================
#define GNCH 16
#define XS_W (GNCH * 7 * 68)
#define AT_ELEMS (49 * 60)
#define GATHER_SMEM (AT_ELEMS * 4 + 2 * XS_W * 2)   // 42224

__global__ void __launch_bounds__(224) gather_kernel(float* __restrict__ out)
{
    extern __shared__ __align__(16) float gsm[];
    float* const at = gsm;
    __half* const xs0 = (__half*)(gsm + AT_ELEMS);
    const int h = blockIdx.x, b = blockIdx.y;
    const int chalf = blockIdx.z * 128;
    const int tid = threadIdx.x;
    const uint32_t xs_sb = smem_to_u32(xs0);

    for (int t = tid; t < 49 * 14; t += 224) {
        int kk = t / 14, p4 = t - kk * 14;
        *reinterpret_cast<float4*>(&at[kk * 60 + p4 * 4]) =
            *reinterpret_cast<const float4*>(
                g_attn + ((size_t)b * NT + kk) * HW + h * WW + p4 * 4);
    }

    auto issueX = [&](int ch, int buf) {
        const __half* xpc = g_xh + (size_t)(b * CC + chalf + ch * GNCH) * XPCH
                          + (size_t)h * XPR;
        const uint32_t dstb = xs_sb + (uint32_t)buf * (XS_W * 2);
#pragma unroll
        for (int it = 0; it < 9; ++it) {
            int t = tid + it * 224;
            if (t < GNCH * 7 * 17) {
                int c = t / 119;
                int r = t - c * 119;
                int i = r / 17;
                int qd = r - i * 17;
                CP8(dstb + (uint32_t)((c * 7 + i) * 68 + qd * 4) * 2,
                    (const char*)(xpc + (size_t)c * XPCH + i * (2 * XPR) + qd * 4));
            }
        }
        CP_COMMIT();
    };

    const int pg = tid % 28, cg = tid / 28;
    const int p0 = pg * 2;
    const int c0 = cg * 2, c1 = c0 + 1;

    issueX(0, 0);

    for (int ch = 0; ch < 8; ++ch) {
        CP_WAIT0();
        __syncthreads();
        if (ch + 1 < 8) issueX(ch + 1, (ch + 1) & 1);

        const __half* xb = xs0 + (ch & 1) * XS_W;
        u64 a0 = 0ull, a1 = 0ull;
#pragma unroll
        for (int i = 0; i < 7; ++i) {
            const __half* xr0 = xb + (c0 * 7 + i) * 68 + p0;
            const __half* xr1 = xb + (c1 * 7 + i) * 68 + p0;
            const float* ar = &at[(i * 7) * 60 + p0];
#pragma unroll
            for (int j = 0; j < 7; ++j) {
                u64 av = lds64(ar + j * 60);
                float2 f0 = __half22float2(
                    *reinterpret_cast<const __half2*>(xr0 + 2 * j));
                float2 f1 = __half22float2(
                    *reinterpret_cast<const __half2*>(xr1 + 2 * j));
                fma2(a0, av, pack2f(f0));
                fma2(a1, av, pack2f(f1));
            }
        }
        size_t ob = (size_t)(b * CC + chalf + ch * GNCH + c0) * HW + h * WW + p0;
        *reinterpret_cast<float2*>(&out[ob])      = unpack2(a0);
        *reinterpret_cast<float2*>(&out[ob + HW]) = unpack2(a1);
        __syncthreads();
    }
}

// =====================================================================
extern "C" void kernel_launch(void* const* d_in, const int* in_sizes, int n_in,
                              void* d_out, int out_size)
{
    const float* x  = (const float*)d_in[0];
    const float* W1 = (const float*)d_in[1];
    const float* b1 = (const float*)d_in[2];
    const float* W2 = (const float*)d_in[3];
    const float* b2 = (const float*)d_in[4];
    for (int i = 0; i < n_in; ++i) {
        switch (in_sizes[i]) {
            case BB * CC * HW: x  = (const float*)d_in[i]; break;
            case CO * CC * NT: W1 = (const float*)d_in[i]; break;
            case CO:           b1 = (const float*)d_in[i]; break;
            case NT * CO:      W2 = (const float*)d_in[i]; break;
            case NT:           b2 = (const float*)d_in[i]; break;
            default: break;
        }
    }
    float* out = (float*)d_out;

    cudaFuncSetAttribute(conv1_mma, cudaFuncAttributeMaxDynamicSharedMemorySize,
                         CONV1_SMEM);
    cudaFuncSetAttribute(gather_kernel, cudaFuncAttributeMaxDynamicSharedMemorySize,
                         GATHER_SMEM);
    prep_all<<<W1T_BLOCKS + XPH_BLOCKS, 256>>>(W1, x);
    conv1_mma<<<dim3(49, KSPL), 256, CONV1_SMEM>>>();
    conv2_softmax_kernel<<<196, 256>>>(W2, b1, b2);
    gather_kernel<<<dim3(56, 4, 2), 224, GATHER_SMEM>>>(out);
}